// round 8
// baseline (speedup 1.0000x reference)
#include <cuda_runtime.h>
#include <cstdint>

#define NB 128
#define NI 512
#define NH 256
#define NOF 512   // O*F = 32*16

// Arch-feature gate: tcgen05 only exists in the sm_103a (arch-specific) pass.
#if defined(__CUDA_ARCH__) && \
    (defined(__CUDA_ARCH_FEAT_SM103_ALL) || defined(__CUDA_ARCH_FEAT_SM101_ALL) || \
     (defined(__CUDA_ARCH_SPECIFIC__) && (__CUDA_ARCH_SPECIFIC__ == 1030)))
#define TC_PATH 1
#else
#define TC_PATH 0
#endif

// ---------------- device scratch (allocation-free rule) ----------------
__device__ float g_U[(size_t)NB * NI * NOF];   // u: [B*I, 512] row-major
__device__ float g_W2[8 * 512 * 32];           // pre-swizzled tf32 B tiles: 8 chunks x 64KB
__device__ float g_vacc[NB * NOF];             // zero-init; squash re-zeros (replay-safe)
__device__ float g_vsq[NB * NOF];

// ---------------- generic helpers ----------------
__device__ __forceinline__ uint32_t smem_u32(const void* p) {
    uint32_t a;
    asm("{ .reg .u64 t; cvta.to.shared.u64 t, %1; cvt.u32.u64 %0, t; }" : "=r"(a) : "l"(p));
    return a;
}
__device__ __forceinline__ float to_tf32(float x) {
    float r;
    asm("cvt.rna.tf32.f32 %0, %1;" : "=f"(r) : "f"(x));
    return r;
}
__device__ __forceinline__ uint32_t sw128(uint32_t off) { return off ^ ((off >> 3) & 0x70); }

// packed f32x2 helpers (fallback GEMM)
__device__ __forceinline__ unsigned long long pack_dup(float a) {
    unsigned long long r;
    asm("mov.b64 %0, {%1, %1};" : "=l"(r) : "f"(a));
    return r;
}
__device__ __forceinline__ void ffma2(unsigned long long& d, unsigned long long a,
                                      unsigned long long b) {
    asm("fma.rn.f32x2 %0, %1, %2, %0;" : "+l"(d) : "l"(a), "l"(b));
}
__device__ __forceinline__ float2 unpack2(unsigned long long v) {
    float2 f;
    asm("mov.b64 {%0, %1}, %2;" : "=f"(f.x), "=f"(f.y) : "l"(v));
    return f;
}

// -------- W -> pre-swizzled tf32 SMEM images: g_W2[ch] = 64KB tile (512 n-rows x 128B) ---
__global__ __launch_bounds__(512) void wt_kernel(const float* __restrict__ W) {
    int k = blockIdx.x, n = threadIdx.x;
    float v = to_tf32(W[(size_t)k * NOF + n]);
    int ch = k >> 5, jj = (k & 31) >> 2, r = k & 3;
    uint32_t byteoff = sw128((uint32_t)n * 128 + jj * 16) + r * 4;
    g_W2[ch * 16384 + (byteoff >> 2)] = v;
}

// ---------------- SMEM layout for the GEMM kernel (per-CTA ~97KB -> 2 CTAs/SM) ----------
#define SMB_TMEM 0
#define SMB_BF0 64
#define SMB_BF1 72
#define SMB_MD0 80
#define SMB_MD1 88
#define SM_CS 512                  // colsum: 64 floats
#define SM_A0 1024                 // A buf0: 16KB
#define SM_A1 17408                // A buf1: 16KB
#define SM_B0 33792                // B buf0: 32KB
#define SM_B1 66560                // B buf1: 32KB
#define GEMM_SMEM (SM_B1 + 32768 + 256)   // 99584; staging (33280B) reuses SM_A0..+B0 region

#if TC_PATH
// ---------------- tcgen05-only PTX helpers ----------------
__device__ __forceinline__ uint32_t elect_one_pred() {
    uint32_t pred;
    asm volatile("{\n\t.reg .pred p;\n\telect.sync _|p, 0xFFFFFFFF;\n\t"
                 "selp.b32 %0, 1, 0, p;\n\t}" : "=r"(pred));
    return pred;
}
#define TCGEN05_ALLOC(sa, n) \
    asm volatile("tcgen05.alloc.cta_group::1.sync.aligned.shared::cta.b32 [%0], %1;" \
                 :: "r"((uint32_t)(sa)), "r"((uint32_t)(n)) : "memory")
#define TCGEN05_DEALLOC(t, n) \
    asm volatile("tcgen05.dealloc.cta_group::1.sync.aligned.b32 %0, %1;" :: "r"(t), "r"((uint32_t)(n)))
#define TCGEN05_RELINQ() \
    asm volatile("tcgen05.relinquish_alloc_permit.cta_group::1.sync.aligned;")
#define TCGEN05_COMMIT(mb) \
    asm volatile("tcgen05.commit.cta_group::1.mbarrier::arrive::one.shared::cluster.b64 [%0];" \
                 :: "r"((uint32_t)(mb)) : "memory")
#define TCGEN05_FENCE_AFTER() asm volatile("tcgen05.fence::after_thread_sync;" ::: "memory")
#define TCGEN05_FENCE_BEFORE() asm volatile("tcgen05.fence::before_thread_sync;" ::: "memory")
#define TCGEN05_WAIT_LD() asm volatile("tcgen05.wait::ld.sync.aligned;" ::: "memory")
#define FENCE_ASYNC_SHARED() asm volatile("fence.proxy.async.shared::cta;" ::: "memory")
#define MBAR_INIT(mb, c) \
    asm volatile("mbarrier.init.shared.b64 [%0], %1;" :: "r"((uint32_t)(mb)), "r"((uint32_t)(c)) : "memory")
#define MBAR_INVAL(mb) \
    asm volatile("mbarrier.inval.shared.b64 [%0];" :: "r"((uint32_t)(mb)) : "memory")
#define MBAR_EXPECT_TX(mb, bytes) \
    asm volatile("mbarrier.arrive.expect_tx.shared.b64 _, [%0], %1;" \
                 :: "r"((uint32_t)(mb)), "r"((uint32_t)(bytes)) : "memory")

__device__ __forceinline__ void mbar_wait_parity(uint32_t mb, uint32_t parity) {
    asm volatile(
        "{\n\t.reg .pred P1;\n\t"
        "WAIT_LOOP_%=:\n\t"
        "mbarrier.try_wait.parity.acquire.cta.shared::cta.b64 P1, [%0], %1, 0x989680;\n\t"
        "@P1 bra.uni WAIT_DONE_%=;\n\t"
        "bra.uni WAIT_LOOP_%=;\n\t"
        "WAIT_DONE_%=:\n\t}"
        :: "r"(mb), "r"(parity) : "memory");
}
__device__ __forceinline__ void bulk_ldg(uint32_t dst, const void* src, uint32_t bytes,
                                         uint32_t mb) {
    asm volatile(
        "cp.async.bulk.shared::cta.global.mbarrier::complete_tx::bytes [%0], [%1], %2, [%3];"
        :: "r"(dst), "l"(src), "r"(bytes), "r"(mb) : "memory");
}

#define LD32X32_X32(r, ta) \
    asm volatile( \
        "tcgen05.ld.sync.aligned.32x32b.x32.b32 " \
        "{%0, %1, %2, %3, %4, %5, %6, %7, %8, %9, %10, %11, %12, %13, %14, %15, " \
        " %16, %17, %18, %19, %20, %21, %22, %23, %24, %25, %26, %27, %28, %29, %30, %31}, [%32];" \
        : "=r"((r)[0]),  "=r"((r)[1]),  "=r"((r)[2]),  "=r"((r)[3]), \
          "=r"((r)[4]),  "=r"((r)[5]),  "=r"((r)[6]),  "=r"((r)[7]), \
          "=r"((r)[8]),  "=r"((r)[9]),  "=r"((r)[10]), "=r"((r)[11]), \
          "=r"((r)[12]), "=r"((r)[13]), "=r"((r)[14]), "=r"((r)[15]), \
          "=r"((r)[16]), "=r"((r)[17]), "=r"((r)[18]), "=r"((r)[19]), \
          "=r"((r)[20]), "=r"((r)[21]), "=r"((r)[22]), "=r"((r)[23]), \
          "=r"((r)[24]), "=r"((r)[25]), "=r"((r)[26]), "=r"((r)[27]), \
          "=r"((r)[28]), "=r"((r)[29]), "=r"((r)[30]), "=r"((r)[31]) \
        : "r"(ta))

__device__ __forceinline__ void mma_tf32_ss(uint32_t d, uint64_t ad, uint64_t bd,
                                            uint32_t idesc, bool en) {
    uint32_t e = en ? 1u : 0u, z = 0u;
    asm volatile(
        "{\n\t.reg .pred p;\n\tsetp.ne.u32 p, %6, 0;\n\t"
        "tcgen05.mma.cta_group::1.kind::tf32 [%0], %1, %2, %3, {%4, %4, %4, %4}, p;\n\t}"
        :: "r"(d), "l"(ad), "l"(bd), "r"(idesc), "r"(z), "r"(z), "r"(e)
        : "memory");
}
__device__ __forceinline__ uint64_t make_desc_sw128(uint32_t base) {
    const uint64_t BASE =
        (uint64_t(2) << 61) | (uint64_t(1) << 46) | (uint64_t(64) << 32) | (uint64_t(1) << 16);
    return BASE | ((uint64_t)(base >> 4) & 0x3FFF);
}
// idesc: dtype F32, atype/btype TF32, N=256, M=128
#define TF32_IDESC (0x10u | (2u << 7) | (2u << 10) | ((256u >> 3) << 17) | ((128u >> 4) << 24))
#endif  // TC_PATH

// -------- GEMM: U[65536,512] = X[65536,256] * W. Tile 128x256, grid (2,512), 2 CTAs/SM --
__global__ __launch_bounds__(512) void gemm_tc(const float* __restrict__ X,
                                               const float* __restrict__ W) {
    extern __shared__ char smem[];
    int tid = threadIdx.x;
    int colBase = blockIdx.x << 8;       // 0 or 256
    int rowBase = blockIdx.y << 7;
    int b = rowBase >> 9;                // batch index

#if TC_PATH
    const uint32_t sb = smem_u32(smem);
    int wid = tid >> 5, lane = tid & 31;

    if (wid == 0) {
        TCGEN05_ALLOC(sb + SMB_TMEM, 256);
        TCGEN05_RELINQ();
    }
    if (tid == 0) {
        MBAR_INIT(sb + SMB_BF0, 1); MBAR_INIT(sb + SMB_BF1, 1);
        MBAR_INIT(sb + SMB_MD0, 1); MBAR_INIT(sb + SMB_MD1, 1);
    }
    __syncthreads();
    uint32_t tmem;
    asm volatile("ld.shared.b32 %0, [%1];" : "=r"(tmem) : "r"(sb + SMB_TMEM));

    // Prologue: A(0) into regs; B(0) sub-image (256 rows x 128B = 32KB) via bulk
    float4 ra[2];
#pragma unroll
    for (int p = 0; p < 2; p++) {
        int u = tid + (p << 9);
        ra[p] = *(const float4*)(X + (size_t)(rowBase + (u >> 3)) * NH + (u & 7) * 4);
    }
    if (tid == 0) {
        MBAR_EXPECT_TX(sb + SMB_BF0, 32768);
        bulk_ldg(sb + SM_B0, g_W2 + (size_t)colBase * 32, 32768, sb + SMB_BF0);
    }

    for (int ch = 0; ch < 8; ch++) {
        int buf = ch & 1;
        uint32_t Aoff = buf ? SM_A1 : SM_A0;
        uint32_t Boff = buf ? SM_B1 : SM_B0;
        uint32_t BFmb = sb + (buf ? SMB_BF1 : SMB_BF0);
        uint32_t MDmb = sb + (buf ? SMB_MD1 : SMB_MD0);

        // A regs -> SMEM (tf32 + SW128)
#pragma unroll
        for (int p = 0; p < 2; p++) {
            int u = tid + (p << 9);
            float4 v = ra[p];
            v.x = to_tf32(v.x); v.y = to_tf32(v.y); v.z = to_tf32(v.z); v.w = to_tf32(v.w);
            *(float4*)(smem + Aoff + sw128((u >> 3) * 128 + (u & 7) * 16)) = v;
        }
        FENCE_ASYNC_SHARED();
        __syncthreads();

        if (wid == 0) {
            uint64_t ad = make_desc_sw128(sb + Aoff);
            uint64_t bd = make_desc_sw128(sb + Boff);
            if (elect_one_pred()) {
                mbar_wait_parity(BFmb, (ch >> 1) & 1);    // B(ch) arrived
#pragma unroll
                for (int k = 0; k < 4; k++)
                    mma_tf32_ss(tmem, ad + k * 2, bd + k * 2, TF32_IDESC, (ch > 0) || (k > 0));
                TCGEN05_COMMIT(MDmb);
            }
        }

        // Prep chunk ch+1: wait MMA(ch-1) frees nb buffers, then overlap loads with MMA(ch)
        if (ch < 7) {
            int nb = (ch + 1) & 1;
            if (ch >= 1)
                mbar_wait_parity(sb + (nb ? SMB_MD1 : SMB_MD0), ((ch - 1) >> 1) & 1);
            int kk = (ch + 1) * 32;
#pragma unroll
            for (int p = 0; p < 2; p++) {
                int u = tid + (p << 9);
                ra[p] = *(const float4*)(X + (size_t)(rowBase + (u >> 3)) * NH + kk + (u & 7) * 4);
            }
            if (tid == 0) {
                uint32_t nBF = sb + (nb ? SMB_BF1 : SMB_BF0);
                MBAR_EXPECT_TX(nBF, 32768);
                bulk_ldg(sb + (nb ? SM_B1 : SM_B0),
                         g_W2 + (size_t)(ch + 1) * 16384 + (size_t)colBase * 32, 32768, nBF);
            }
        }
    }
    mbar_wait_parity(sb + SMB_MD0, 1);   // last MMA on buf0 (ch=6, phase 3)
    mbar_wait_parity(sb + SMB_MD1, 1);   // last MMA on buf1 (ch=7, phase 3)
    TCGEN05_FENCE_AFTER();

    // Epilogue: 4 chunks of 64 cols. TMEM -> smt (pad 65, conflict-free) -> GMEM + colsums
    float* smt = (float*)(smem + SM_A0);      // 128 x 65 floats (33280B; overlaps A0,A1,B0-part)
    float* colsum = (float*)(smem + SM_CS);   // 64 floats
    for (int cc = 0; cc < 4; cc++) {
        if (tid < 64) colsum[tid] = 0.f;
        __syncthreads();
        if (wid < 4) {
            uint32_t regs[64];
            LD32X32_X32(regs, tmem + cc * 64);
            LD32X32_X32(regs + 32, tmem + cc * 64 + 32);
            TCGEN05_WAIT_LD();
            TCGEN05_FENCE_BEFORE();
            float* dst = smt + (wid * 32 + lane) * 65;
#pragma unroll
            for (int c = 0; c < 64; c++) dst[c] = __uint_as_float(regs[c]);
        }
        __syncthreads();
        int c = tid & 63, r0 = tid >> 6;
        float lsum = 0.f;
#pragma unroll
        for (int p = 0; p < 16; p++) {
            int r = r0 + p * 8;
            float v = smt[r * 65 + c];
            lsum += v;
            g_U[(size_t)(rowBase + r) * NOF + colBase + cc * 64 + c] = v;
        }
        atomicAdd(&colsum[c], lsum);
        __syncthreads();
        if (tid < 64)
            atomicAdd(&g_vacc[b * NOF + colBase + cc * 64 + tid], colsum[tid] * (1.0f / 32.0f));
    }

    __syncthreads();
    if (tid == 0) {
        MBAR_INVAL(sb + SMB_BF0); MBAR_INVAL(sb + SMB_BF1);
        MBAR_INVAL(sb + SMB_MD0); MBAR_INVAL(sb + SMB_MD1);
    }
    __syncthreads();
    if (wid == 0) TCGEN05_DEALLOC(tmem, 256);

#else  // ---------- FFMA2 fallback (plain sm_103 pass; same outputs, never selected) -----
    float* As = (float*)(smem);            // [8][128]
    float* Bs = (float*)(smem + 4096);     // [8][128]
    float* colsum = (float*)(smem + 8192); // [128]
    int tr = tid >> 5, tc = tid & 31;

    for (int ct = 0; ct < 2; ct++) {
        int colBase2 = colBase + ct * 128;
        unsigned long long acc[8][2];
#pragma unroll
        for (int i = 0; i < 8; i++) { acc[i][0] = 0ull; acc[i][1] = 0ull; }
        if (tid < 128) colsum[tid] = 0.f;
        __syncthreads();

        for (int kt = 0; kt < NH; kt += 8) {
#pragma unroll
            for (int q = 0; q < 2; q++) {
                int u = tid + q * 512;
                As[(u & 7) * 128 + (u >> 3)] =
                    X[(size_t)(rowBase + (u >> 3)) * NH + kt + (u & 7)];
                Bs[(u >> 7) * 128 + (u & 127)] =
                    W[(size_t)(kt + (u >> 7)) * NOF + colBase2 + (u & 127)];
            }
            __syncthreads();
#pragma unroll
            for (int k = 0; k < 8; k++) {
                const ulonglong2* bp = (const ulonglong2*)&Bs[k * 128 + tc * 4];
                ulonglong2 bb = bp[0];
                const float* ap = &As[k * 128 + tr * 8];
#pragma unroll
                for (int i = 0; i < 8; i++) {
                    unsigned long long m2 = pack_dup(ap[i]);
                    ffma2(acc[i][0], m2, bb.x);
                    ffma2(acc[i][1], m2, bb.y);
                }
            }
            __syncthreads();
        }
        float cs[4] = {0.f, 0.f, 0.f, 0.f};
#pragma unroll
        for (int i = 0; i < 8; i++) {
            float2 c0 = unpack2(acc[i][0]);
            float2 c1 = unpack2(acc[i][1]);
            *(float4*)(g_U + (size_t)(rowBase + tr * 8 + i) * NOF + colBase2 + tc * 4) =
                make_float4(c0.x, c0.y, c1.x, c1.y);
            cs[0] += c0.x; cs[1] += c0.y; cs[2] += c1.x; cs[3] += c1.y;
        }
#pragma unroll
        for (int j = 0; j < 4; j++) atomicAdd(&colsum[tc * 4 + j], cs[j]);
        __syncthreads();
        if (tid < 128)
            atomicAdd(&g_vacc[b * NOF + colBase2 + tid], colsum[tid] * (1.0f / 32.0f));
        __syncthreads();
    }
#endif
}

// ---------------- Squash v1: g_vsq = squash(g_vacc); re-zero g_vacc (replay-safe) --------
__global__ __launch_bounds__(512) void squash_kernel() {
    int idx = blockIdx.x * NOF + threadIdx.x;
    float val = g_vacc[idx];
    g_vacc[idx] = 0.f;
    float n2 = val * val;
#pragma unroll
    for (int m = 8; m > 0; m >>= 1)
        n2 += __shfl_xor_sync(~0u, n2, m);
    float scale = sqrtf(n2) / (1.0f + n2);
    g_vsq[idx] = val * scale;
}

// -------- Fused routing iters 2+3: grid=NB (one CTA/batch), block=512 --------------------
__global__ __launch_bounds__(512) void route_fused(float* __restrict__ out) {
    __shared__ float vs[NOF];
    __shared__ float scl[32];
    int b = blockIdx.x;
    int tid = threadIdx.x, warp = tid >> 5, lane = tid & 31;

    float4 vr[4];
    {
        const float4* vp = (const float4*)(g_vsq + b * NOF);
#pragma unroll
        for (int s = 0; s < 4; s++) vr[s] = vp[s * 32 + lane];
    }
    const float* Ub = g_U + (size_t)b * NI * NOF;

    for (int it = 0; it < 2; it++) {
        vs[tid] = 0.f;
        __syncthreads();

        float4 acc[4];
#pragma unroll
        for (int s = 0; s < 4; s++) acc[s] = make_float4(0.f, 0.f, 0.f, 0.f);

        for (int jj = 0; jj < 32; jj += 2) {
            int i0 = (warp << 5) + jj;
            const float4* up = (const float4*)(Ub + (size_t)i0 * NOF);
            float4 u0 = up[lane], u1 = up[32 + lane], u2 = up[64 + lane], u3 = up[96 + lane];
            float4 w0 = up[128 + lane], w1 = up[160 + lane], w2 = up[192 + lane], w3 = up[224 + lane];

            float a0 = u0.x * vr[0].x + u0.y * vr[0].y + u0.z * vr[0].z + u0.w * vr[0].w;
            float a1 = u1.x * vr[1].x + u1.y * vr[1].y + u1.z * vr[1].z + u1.w * vr[1].w;
            float a2 = u2.x * vr[2].x + u2.y * vr[2].y + u2.z * vr[2].z + u2.w * vr[2].w;
            float a3 = u3.x * vr[3].x + u3.y * vr[3].y + u3.z * vr[3].z + u3.w * vr[3].w;
            float d0 = w0.x * vr[0].x + w0.y * vr[0].y + w0.z * vr[0].z + w0.w * vr[0].w;
            float d1 = w1.x * vr[1].x + w1.y * vr[1].y + w1.z * vr[1].z + w1.w * vr[1].w;
            float d2 = w2.x * vr[2].x + w2.y * vr[2].y + w2.z * vr[2].z + w2.w * vr[2].w;
            float d3 = w3.x * vr[3].x + w3.y * vr[3].y + w3.z * vr[3].z + w3.w * vr[3].w;

            a0 += __shfl_xor_sync(~0u, a0, 1); d0 += __shfl_xor_sync(~0u, d0, 1);
            a1 += __shfl_xor_sync(~0u, a1, 1); d1 += __shfl_xor_sync(~0u, d1, 1);
            a2 += __shfl_xor_sync(~0u, a2, 1); d2 += __shfl_xor_sync(~0u, d2, 1);
            a3 += __shfl_xor_sync(~0u, a3, 1); d3 += __shfl_xor_sync(~0u, d3, 1);
            a0 += __shfl_xor_sync(~0u, a0, 2); d0 += __shfl_xor_sync(~0u, d0, 2);
            a1 += __shfl_xor_sync(~0u, a1, 2); d1 += __shfl_xor_sync(~0u, d1, 2);
            a2 += __shfl_xor_sync(~0u, a2, 2); d2 += __shfl_xor_sync(~0u, d2, 2);
            a3 += __shfl_xor_sync(~0u, a3, 2); d3 += __shfl_xor_sync(~0u, d3, 2);

            // softmax without max-shift (logits bounded)
            float ea0 = __expf(a0), ea1 = __expf(a1), ea2 = __expf(a2), ea3 = __expf(a3);
            float ed0 = __expf(d0), ed1 = __expf(d1), ed2 = __expf(d2), ed3 = __expf(d3);
            float sa = ea0 + ea1 + ea2 + ea3;
            float sd = ed0 + ed1 + ed2 + ed3;
            sa += __shfl_xor_sync(~0u, sa, 4);  sd += __shfl_xor_sync(~0u, sd, 4);
            sa += __shfl_xor_sync(~0u, sa, 8);  sd += __shfl_xor_sync(~0u, sd, 8);
            sa += __shfl_xor_sync(~0u, sa, 16); sd += __shfl_xor_sync(~0u, sd, 16);
            float ia = 1.0f / sa, id = 1.0f / sd;
            float c0 = ea0 * ia, c1 = ea1 * ia, c2 = ea2 * ia, c3 = ea3 * ia;
            float e0 = ed0 * id, e1 = ed1 * id, e2 = ed2 * id, e3 = ed3 * id;

            acc[0].x += c0 * u0.x + e0 * w0.x; acc[0].y += c0 * u0.y + e0 * w0.y;
            acc[0].z += c0 * u0.z + e0 * w0.z; acc[0].w += c0 * u0.w + e0 * w0.w;
            acc[1].x += c1 * u1.x + e1 * w1.x; acc[1].y += c1 * u1.y + e1 * w1.y;
            acc[1].z += c1 * u1.z + e1 * w1.z; acc[1].w += c1 * u1.w + e1 * w1.w;
            acc[2].x += c2 * u2.x + e2 * w2.x; acc[2].y += c2 * u2.y + e2 * w2.y;
            acc[2].z += c2 * u2.z + e2 * w2.z; acc[2].w += c2 * u2.w + e2 * w2.w;
            acc[3].x += c3 * u3.x + e3 * w3.x; acc[3].y += c3 * u3.y + e3 * w3.y;
            acc[3].z += c3 * u3.z + e3 * w3.z; acc[3].w += c3 * u3.w + e3 * w3.w;
        }

#pragma unroll
        for (int s = 0; s < 4; s++) {
            int base = (s * 8 + (lane >> 2)) * 16 + (lane & 3) * 4;
            atomicAdd(&vs[base + 0], acc[s].x);
            atomicAdd(&vs[base + 1], acc[s].y);
            atomicAdd(&vs[base + 2], acc[s].z);
            atomicAdd(&vs[base + 3], acc[s].w);
        }
        __syncthreads();

        if (tid < 32) {
            float n2 = 0.f;
#pragma unroll
            for (int f = 0; f < 16; f++) { float t = vs[tid * 16 + f]; n2 += t * t; }
            scl[tid] = sqrtf(n2) / (1.0f + n2);
        }
        __syncthreads();

        if (it == 0) {
#pragma unroll
            for (int s = 0; s < 4; s++) {
                int o = s * 8 + (lane >> 2);
                int base = o * 16 + (lane & 3) * 4;
                float sc = scl[o];
                vr[s] = make_float4(vs[base] * sc, vs[base + 1] * sc,
                                    vs[base + 2] * sc, vs[base + 3] * sc);
            }
            __syncthreads();
        } else {
            out[b * NOF + tid] = vs[tid] * scl[tid >> 4];
        }
    }
}

extern "C" void kernel_launch(void* const* d_in, const int* in_sizes, int n_in,
                              void* d_out, int out_size) {
    const float* x = (const float*)d_in[0];   // [128, 512, 256]
    const float* W = (const float*)d_in[1];   // [1, 256, 512]
    float* out = (float*)d_out;               // [128, 32, 16]

    cudaFuncSetAttribute(gemm_tc, cudaFuncAttributeMaxDynamicSharedMemorySize, GEMM_SMEM);

    wt_kernel<<<256, 512>>>(W);                    // pre-swizzled tf32 B tiles
    gemm_tc<<<dim3(2, 512), 512, GEMM_SMEM>>>(x, W);  // U + fused iter-1 colsums
    squash_kernel<<<NB, 512>>>();                  // v1 -> g_vsq (zeros g_vacc)
    route_fused<<<NB, 512>>>(out);                 // iters 2+3 fused -> out
}

// round 9
// speedup vs baseline: 1.1979x; 1.1979x over previous
#include <cuda_runtime.h>
#include <cuda_fp16.h>
#include <cstdint>

#define NB 128
#define NI 512
#define NH 256
#define NOF 512   // O*F = 32*16

// Arch-feature gate: tcgen05 only exists in the sm_103a (arch-specific) pass.
#if defined(__CUDA_ARCH__) && \
    (defined(__CUDA_ARCH_FEAT_SM103_ALL) || defined(__CUDA_ARCH_FEAT_SM101_ALL) || \
     (defined(__CUDA_ARCH_SPECIFIC__) && (__CUDA_ARCH_SPECIFIC__ == 1030)))
#define TC_PATH 1
#else
#define TC_PATH 0
#endif

// ---------------- device scratch (allocation-free rule) ----------------
__device__ __half g_Uh[(size_t)NB * NI * NOF]; // u in fp16: [B*I, 512] row-major (64MB)
__device__ float g_W2[8 * 512 * 32];           // pre-swizzled tf32 B tiles: 8 chunks x 64KB
__device__ float g_vacc[NB * NOF];             // zero-init; squash re-zeros (replay-safe)
__device__ float g_vsq[NB * NOF];

// ---------------- generic helpers ----------------
__device__ __forceinline__ uint32_t smem_u32(const void* p) {
    uint32_t a;
    asm("{ .reg .u64 t; cvta.to.shared.u64 t, %1; cvt.u32.u64 %0, t; }" : "=r"(a) : "l"(p));
    return a;
}
__device__ __forceinline__ float to_tf32(float x) {
    float r;
    asm("cvt.rna.tf32.f32 %0, %1;" : "=f"(r) : "f"(x));
    return r;
}
__device__ __forceinline__ uint32_t sw128(uint32_t off) { return off ^ ((off >> 3) & 0x70); }

// packed f32x2 helpers (fallback GEMM)
__device__ __forceinline__ unsigned long long pack_dup(float a) {
    unsigned long long r;
    asm("mov.b64 %0, {%1, %1};" : "=l"(r) : "f"(a));
    return r;
}
__device__ __forceinline__ void ffma2(unsigned long long& d, unsigned long long a,
                                      unsigned long long b) {
    asm("fma.rn.f32x2 %0, %1, %2, %0;" : "+l"(d) : "l"(a), "l"(b));
}
__device__ __forceinline__ float2 unpack2(unsigned long long v) {
    float2 f;
    asm("mov.b64 {%0, %1}, %2;" : "=f"(f.x), "=f"(f.y) : "l"(v));
    return f;
}
// uint4 (8 fp16) -> 8 floats
__device__ __forceinline__ void cvt8(float* d, uint4 v) {
    __half2* h = (__half2*)&v;
#pragma unroll
    for (int k = 0; k < 4; k++) {
        float2 f = __half22float2(h[k]);
        d[2 * k] = f.x; d[2 * k + 1] = f.y;
    }
}
__device__ __forceinline__ float dot8(const float* a, const float* b) {
    float s = 0.f;
#pragma unroll
    for (int j = 0; j < 8; j++) s += a[j] * b[j];
    return s;
}

// -------- W -> pre-swizzled tf32 SMEM images: g_W2[ch] = 64KB tile (512 n-rows x 128B) ---
__global__ __launch_bounds__(512) void wt_kernel(const float* __restrict__ W) {
    int k = blockIdx.x, n = threadIdx.x;
    float v = to_tf32(W[(size_t)k * NOF + n]);
    int ch = k >> 5, jj = (k & 31) >> 2, r = k & 3;
    uint32_t byteoff = sw128((uint32_t)n * 128 + jj * 16) + r * 4;
    g_W2[ch * 16384 + (byteoff >> 2)] = v;
}

// ---------------- SMEM layout for the GEMM kernel (R6 config: 1 CTA/SM) ----------------
#define SMB_TMEM 0
#define SMB_BF0 64
#define SMB_BF1 72
#define SMB_MD0 80
#define SMB_MD1 88
#define SM_CS 512                  // colsum: 64 floats
#define SM_A0 1024
#define SM_A1 (SM_A0 + 16384)
#define SM_B0 (SM_A1 + 16384)      // 33792
#define SM_B1 (SM_B0 + 65536)      // 99328
#define GEMM_SMEM (SM_B1 + 65536 + 256)

#if TC_PATH
// ---------------- tcgen05-only PTX helpers ----------------
__device__ __forceinline__ uint32_t elect_one_pred() {
    uint32_t pred;
    asm volatile("{\n\t.reg .pred p;\n\telect.sync _|p, 0xFFFFFFFF;\n\t"
                 "selp.b32 %0, 1, 0, p;\n\t}" : "=r"(pred));
    return pred;
}
#define TCGEN05_ALLOC(sa, n) \
    asm volatile("tcgen05.alloc.cta_group::1.sync.aligned.shared::cta.b32 [%0], %1;" \
                 :: "r"((uint32_t)(sa)), "r"((uint32_t)(n)) : "memory")
#define TCGEN05_DEALLOC(t, n) \
    asm volatile("tcgen05.dealloc.cta_group::1.sync.aligned.b32 %0, %1;" :: "r"(t), "r"((uint32_t)(n)))
#define TCGEN05_RELINQ() \
    asm volatile("tcgen05.relinquish_alloc_permit.cta_group::1.sync.aligned;")
#define TCGEN05_COMMIT(mb) \
    asm volatile("tcgen05.commit.cta_group::1.mbarrier::arrive::one.shared::cluster.b64 [%0];" \
                 :: "r"((uint32_t)(mb)) : "memory")
#define TCGEN05_FENCE_AFTER() asm volatile("tcgen05.fence::after_thread_sync;" ::: "memory")
#define TCGEN05_FENCE_BEFORE() asm volatile("tcgen05.fence::before_thread_sync;" ::: "memory")
#define TCGEN05_WAIT_LD() asm volatile("tcgen05.wait::ld.sync.aligned;" ::: "memory")
#define FENCE_ASYNC_SHARED() asm volatile("fence.proxy.async.shared::cta;" ::: "memory")
#define MBAR_INIT(mb, c) \
    asm volatile("mbarrier.init.shared.b64 [%0], %1;" :: "r"((uint32_t)(mb)), "r"((uint32_t)(c)) : "memory")
#define MBAR_INVAL(mb) \
    asm volatile("mbarrier.inval.shared.b64 [%0];" :: "r"((uint32_t)(mb)) : "memory")
#define MBAR_EXPECT_TX(mb, bytes) \
    asm volatile("mbarrier.arrive.expect_tx.shared.b64 _, [%0], %1;" \
                 :: "r"((uint32_t)(mb)), "r"((uint32_t)(bytes)) : "memory")

__device__ __forceinline__ void mbar_wait_parity(uint32_t mb, uint32_t parity) {
    asm volatile(
        "{\n\t.reg .pred P1;\n\t"
        "WAIT_LOOP_%=:\n\t"
        "mbarrier.try_wait.parity.acquire.cta.shared::cta.b64 P1, [%0], %1, 0x989680;\n\t"
        "@P1 bra.uni WAIT_DONE_%=;\n\t"
        "bra.uni WAIT_LOOP_%=;\n\t"
        "WAIT_DONE_%=:\n\t}"
        :: "r"(mb), "r"(parity) : "memory");
}
__device__ __forceinline__ void bulk_ldg(uint32_t dst, const void* src, uint32_t bytes,
                                         uint32_t mb) {
    asm volatile(
        "cp.async.bulk.shared::cta.global.mbarrier::complete_tx::bytes [%0], [%1], %2, [%3];"
        :: "r"(dst), "l"(src), "r"(bytes), "r"(mb) : "memory");
}

#define LD32X32_X32(r, ta) \
    asm volatile( \
        "tcgen05.ld.sync.aligned.32x32b.x32.b32 " \
        "{%0, %1, %2, %3, %4, %5, %6, %7, %8, %9, %10, %11, %12, %13, %14, %15, " \
        " %16, %17, %18, %19, %20, %21, %22, %23, %24, %25, %26, %27, %28, %29, %30, %31}, [%32];" \
        : "=r"((r)[0]),  "=r"((r)[1]),  "=r"((r)[2]),  "=r"((r)[3]), \
          "=r"((r)[4]),  "=r"((r)[5]),  "=r"((r)[6]),  "=r"((r)[7]), \
          "=r"((r)[8]),  "=r"((r)[9]),  "=r"((r)[10]), "=r"((r)[11]), \
          "=r"((r)[12]), "=r"((r)[13]), "=r"((r)[14]), "=r"((r)[15]), \
          "=r"((r)[16]), "=r"((r)[17]), "=r"((r)[18]), "=r"((r)[19]), \
          "=r"((r)[20]), "=r"((r)[21]), "=r"((r)[22]), "=r"((r)[23]), \
          "=r"((r)[24]), "=r"((r)[25]), "=r"((r)[26]), "=r"((r)[27]), \
          "=r"((r)[28]), "=r"((r)[29]), "=r"((r)[30]), "=r"((r)[31]) \
        : "r"(ta))

__device__ __forceinline__ void mma_tf32_ss(uint32_t d, uint64_t ad, uint64_t bd,
                                            uint32_t idesc, bool en) {
    uint32_t e = en ? 1u : 0u, z = 0u;
    asm volatile(
        "{\n\t.reg .pred p;\n\tsetp.ne.u32 p, %6, 0;\n\t"
        "tcgen05.mma.cta_group::1.kind::tf32 [%0], %1, %2, %3, {%4, %4, %4, %4}, p;\n\t}"
        :: "r"(d), "l"(ad), "l"(bd), "r"(idesc), "r"(z), "r"(z), "r"(e)
        : "memory");
}
__device__ __forceinline__ uint64_t make_desc_sw128(uint32_t base) {
    const uint64_t BASE =
        (uint64_t(2) << 61) | (uint64_t(1) << 46) | (uint64_t(64) << 32) | (uint64_t(1) << 16);
    return BASE | ((uint64_t)(base >> 4) & 0x3FFF);
}
// idesc: dtype F32, atype/btype TF32, N=256, M=128
#define TF32_IDESC (0x10u | (2u << 7) | (2u << 10) | ((256u >> 3) << 17) | ((128u >> 4) << 24))
#endif  // TC_PATH

// -------- GEMM: Uh[65536,512] = X[65536,256] * W  (tile 128x512, fused iter-1 colsums) --
// grid = 512, block = 512, 1 CTA/SM (R6 config, best measured). U stored fp16.
__global__ __launch_bounds__(512, 1) void gemm_tc(const float* __restrict__ X,
                                                  const float* __restrict__ W) {
    extern __shared__ char smem[];
    int tid = threadIdx.x;
    int rowBase = blockIdx.x << 7;
    int b = rowBase >> 9;

#if TC_PATH
    const uint32_t sb = smem_u32(smem);
    int wid = tid >> 5, lane = tid & 31;

    if (wid == 0) {
        TCGEN05_ALLOC(sb + SMB_TMEM, 512);
        TCGEN05_RELINQ();
    }
    if (tid == 0) {
        MBAR_INIT(sb + SMB_BF0, 1); MBAR_INIT(sb + SMB_BF1, 1);
        MBAR_INIT(sb + SMB_MD0, 1); MBAR_INIT(sb + SMB_MD1, 1);
    }
    __syncthreads();
    uint32_t tmem;
    asm volatile("ld.shared.b32 %0, [%1];" : "=r"(tmem) : "r"(sb + SMB_TMEM));

    // Prologue: A(0) regs, B(0) bulk
    float4 ra[2];
#pragma unroll
    for (int p = 0; p < 2; p++) {
        int u = tid + (p << 9);
        ra[p] = *(const float4*)(X + (size_t)(rowBase + (u >> 3)) * NH + (u & 7) * 4);
    }
    if (tid == 0) {
        MBAR_EXPECT_TX(sb + SMB_BF0, 65536);
        bulk_ldg(sb + SM_B0, g_W2, 65536, sb + SMB_BF0);
    }

    for (int ch = 0; ch < 8; ch++) {
        int buf = ch & 1;
        uint32_t Aoff = buf ? SM_A1 : SM_A0;
        uint32_t Boff = buf ? SM_B1 : SM_B0;
        uint32_t BFmb = sb + (buf ? SMB_BF1 : SMB_BF0);
        uint32_t MDmb = sb + (buf ? SMB_MD1 : SMB_MD0);

        // A regs -> SMEM (tf32 + SW128)
#pragma unroll
        for (int p = 0; p < 2; p++) {
            int u = tid + (p << 9);
            float4 v = ra[p];
            v.x = to_tf32(v.x); v.y = to_tf32(v.y); v.z = to_tf32(v.z); v.w = to_tf32(v.w);
            *(float4*)(smem + Aoff + sw128((u >> 3) * 128 + (u & 7) * 16)) = v;
        }
        FENCE_ASYNC_SHARED();
        __syncthreads();

        if (wid == 0) {
            uint64_t ad = make_desc_sw128(sb + Aoff);
            uint64_t bd = make_desc_sw128(sb + Boff);
            if (elect_one_pred()) {
                mbar_wait_parity(BFmb, (ch >> 1) & 1);    // B(ch) arrived
#pragma unroll
                for (int h = 0; h < 2; h++)
#pragma unroll
                    for (int k = 0; k < 4; k++)
                        mma_tf32_ss(tmem + h * 256, ad + k * 2, bd + h * 2048 + k * 2,
                                    TF32_IDESC, (ch > 0) || (k > 0));
                TCGEN05_COMMIT(MDmb);
            }
        }

        // Prep chunk ch+1: wait MMA(ch-1) (frees nbuf), overlap loads with MMA(ch)
        if (ch < 7) {
            int nb = (ch + 1) & 1;
            if (ch >= 1)
                mbar_wait_parity(sb + (nb ? SMB_MD1 : SMB_MD0), ((ch - 1) >> 1) & 1);
            int kk = (ch + 1) * 32;
#pragma unroll
            for (int p = 0; p < 2; p++) {
                int u = tid + (p << 9);
                ra[p] = *(const float4*)(X + (size_t)(rowBase + (u >> 3)) * NH + kk + (u & 7) * 4);
            }
            if (tid == 0) {
                uint32_t nBF = sb + (nb ? SMB_BF1 : SMB_BF0);
                MBAR_EXPECT_TX(nBF, 65536);
                bulk_ldg(sb + (nb ? SM_B1 : SM_B0), g_W2 + (ch + 1) * 16384, 65536, nBF);
            }
        }
    }
    mbar_wait_parity(sb + SMB_MD0, 1);
    mbar_wait_parity(sb + SMB_MD1, 1);
    TCGEN05_FENCE_AFTER();

    // Epilogue: 8 chunks of 64 cols. TMEM -> smt (pad 65) -> half2 GMEM + colsums.
    float* smt = (float*)(smem + SM_A0);      // 128 x 65 floats
    float* colsum = (float*)(smem + SM_CS);   // 64 floats
    for (int cc = 0; cc < 8; cc++) {
        if (tid < 64) colsum[tid] = 0.f;
        __syncthreads();
        if (wid < 4) {
            uint32_t regs[64];
            LD32X32_X32(regs, tmem + cc * 64);
            LD32X32_X32(regs + 32, tmem + cc * 64 + 32);
            TCGEN05_WAIT_LD();
            TCGEN05_FENCE_BEFORE();
            float* dst = smt + (wid * 32 + lane) * 65;
#pragma unroll
            for (int c = 0; c < 64; c++) dst[c] = __uint_as_float(regs[c]);
        }
        __syncthreads();
        int c2 = tid & 31, r0 = tid >> 5;     // col pair, 16 row groups
        float ls0 = 0.f, ls1 = 0.f;
        __half2* Uh2 = (__half2*)g_Uh;
#pragma unroll
        for (int p = 0; p < 8; p++) {
            int r = r0 + p * 16;
            float va = smt[r * 65 + 2 * c2];
            float vb = smt[r * 65 + 2 * c2 + 1];
            ls0 += va; ls1 += vb;
            Uh2[(size_t)(rowBase + r) * 256 + cc * 32 + c2] = __floats2half2_rn(va, vb);
        }
        atomicAdd(&colsum[2 * c2], ls0);
        atomicAdd(&colsum[2 * c2 + 1], ls1);
        __syncthreads();
        if (tid < 64)
            atomicAdd(&g_vacc[b * NOF + cc * 64 + tid], colsum[tid] * (1.0f / 32.0f));
    }

    __syncthreads();
    if (tid == 0) {
        MBAR_INVAL(sb + SMB_BF0); MBAR_INVAL(sb + SMB_BF1);
        MBAR_INVAL(sb + SMB_MD0); MBAR_INVAL(sb + SMB_MD1);
    }
    __syncthreads();
    if (wid == 0) TCGEN05_DEALLOC(tmem, 512);

#else  // ---------- FFMA2 fallback (plain sm_103 pass; same outputs, never selected) -----
    float* As = (float*)(smem);            // [8][128]
    float* Bs = (float*)(smem + 4096);     // [8][128]
    float* colsum = (float*)(smem + 8192); // [128]
    int tr = tid >> 5, tc = tid & 31;

    for (int ct = 0; ct < 4; ct++) {
        int colBase2 = ct * 128;
        unsigned long long acc[8][2];
#pragma unroll
        for (int i = 0; i < 8; i++) { acc[i][0] = 0ull; acc[i][1] = 0ull; }
        if (tid < 128) colsum[tid] = 0.f;
        __syncthreads();

        for (int kt = 0; kt < NH; kt += 8) {
#pragma unroll
            for (int q = 0; q < 2; q++) {
                int u = tid + q * 512;
                As[(u & 7) * 128 + (u >> 3)] =
                    X[(size_t)(rowBase + (u >> 3)) * NH + kt + (u & 7)];
                Bs[(u >> 7) * 128 + (u & 127)] =
                    W[(size_t)(kt + (u >> 7)) * NOF + colBase2 + (u & 127)];
            }
            __syncthreads();
#pragma unroll
            for (int k = 0; k < 8; k++) {
                const ulonglong2* bp = (const ulonglong2*)&Bs[k * 128 + tc * 4];
                ulonglong2 bb = bp[0];
                const float* ap = &As[k * 128 + tr * 8];
#pragma unroll
                for (int i = 0; i < 8; i++) {
                    unsigned long long m2 = pack_dup(ap[i]);
                    ffma2(acc[i][0], m2, bb.x);
                    ffma2(acc[i][1], m2, bb.y);
                }
            }
            __syncthreads();
        }
        float cs[4] = {0.f, 0.f, 0.f, 0.f};
#pragma unroll
        for (int i = 0; i < 8; i++) {
            float2 c0 = unpack2(acc[i][0]);
            float2 c1 = unpack2(acc[i][1]);
            __half2* Uh2 = (__half2*)g_Uh;
            size_t base = (size_t)(rowBase + tr * 8 + i) * 256 + (colBase2 + tc * 4) / 2;
            Uh2[base] = __floats2half2_rn(c0.x, c0.y);
            Uh2[base + 1] = __floats2half2_rn(c1.x, c1.y);
            cs[0] += c0.x; cs[1] += c0.y; cs[2] += c1.x; cs[3] += c1.y;
        }
#pragma unroll
        for (int j = 0; j < 4; j++) atomicAdd(&colsum[tc * 4 + j], cs[j]);
        __syncthreads();
        if (tid < 128)
            atomicAdd(&g_vacc[b * NOF + colBase2 + tid], colsum[tid] * (1.0f / 32.0f));
        __syncthreads();
    }
#endif
}

// ---------------- Squash v1: g_vsq = squash(g_vacc); re-zero g_vacc (replay-safe) --------
__global__ __launch_bounds__(512) void squash_kernel() {
    int idx = blockIdx.x * NOF + threadIdx.x;
    float val = g_vacc[idx];
    g_vacc[idx] = 0.f;
    float n2 = val * val;
#pragma unroll
    for (int m = 8; m > 0; m >>= 1)
        n2 += __shfl_xor_sync(~0u, n2, m);
    float scale = sqrtf(n2) / (1.0f + n2);
    g_vsq[idx] = val * scale;
}

// -------- Fused routing iters 2+3 on fp16 U: grid=NB (one CTA/batch), block=512 ----------
// Lane mapping per uint4 load s (0,1): elems e = s*256 + lane*8 + j
//   -> o = s*16 + (lane>>1), f = (lane&1)*8 + j.
__global__ __launch_bounds__(512) void route_fused(float* __restrict__ out) {
    __shared__ float vs[NOF];
    __shared__ float scl[32];
    int b = blockIdx.x;
    int tid = threadIdx.x, warp = tid >> 5, lane = tid & 31;
    int o0 = lane >> 1, o1 = 16 + (lane >> 1);
    int fb = (lane & 1) << 3;

    float vr0[8], vr1[8];
    {
        const float* vp = g_vsq + b * NOF;
        // o0*16 + fb == lane*8 ; o1*16 + fb == 256 + lane*8  (coalesced)
        float4 t0 = *(const float4*)(vp + lane * 8);
        float4 t1 = *(const float4*)(vp + lane * 8 + 4);
        float4 t2 = *(const float4*)(vp + 256 + lane * 8);
        float4 t3 = *(const float4*)(vp + 256 + lane * 8 + 4);
        vr0[0] = t0.x; vr0[1] = t0.y; vr0[2] = t0.z; vr0[3] = t0.w;
        vr0[4] = t1.x; vr0[5] = t1.y; vr0[6] = t1.z; vr0[7] = t1.w;
        vr1[0] = t2.x; vr1[1] = t2.y; vr1[2] = t2.z; vr1[3] = t2.w;
        vr1[4] = t3.x; vr1[5] = t3.y; vr1[6] = t3.z; vr1[7] = t3.w;
    }
    const __half* Ub = g_Uh + (size_t)b * NI * NOF;

    for (int it = 0; it < 2; it++) {
        vs[tid] = 0.f;
        __syncthreads();

        float acc0[8], acc1[8];
#pragma unroll
        for (int j = 0; j < 8; j++) { acc0[j] = 0.f; acc1[j] = 0.f; }

        for (int jj = 0; jj < 32; jj += 2) {
            int i0 = (warp << 5) + jj;
            const uint4* up = (const uint4*)(Ub + (size_t)i0 * NOF);
            // row i0: s0, s1 ; row i0+1: s0, s1   (each uint4 = 8 fp16)
            uint4 xa = up[lane], xb = up[32 + lane];
            uint4 ya = up[64 + lane], yb = up[96 + lane];
            float ua[8], ub[8], va[8], vb[8];
            cvt8(ua, xa); cvt8(ub, xb); cvt8(va, ya); cvt8(vb, yb);

            float b0 = dot8(ua, vr0), b1 = dot8(ub, vr1);
            float d0 = dot8(va, vr0), d1 = dot8(vb, vr1);
            b0 += __shfl_xor_sync(~0u, b0, 1);
            b1 += __shfl_xor_sync(~0u, b1, 1);
            d0 += __shfl_xor_sync(~0u, d0, 1);
            d1 += __shfl_xor_sync(~0u, d1, 1);

            // softmax without max-shift (logits bounded; validated R6)
            float e00 = __expf(b0), e01 = __expf(b1);
            float e10 = __expf(d0), e11 = __expf(d1);
            float s0 = e00 + e01, s1 = e10 + e11;
            s0 += __shfl_xor_sync(~0u, s0, 2);  s1 += __shfl_xor_sync(~0u, s1, 2);
            s0 += __shfl_xor_sync(~0u, s0, 4);  s1 += __shfl_xor_sync(~0u, s1, 4);
            s0 += __shfl_xor_sync(~0u, s0, 8);  s1 += __shfl_xor_sync(~0u, s1, 8);
            s0 += __shfl_xor_sync(~0u, s0, 16); s1 += __shfl_xor_sync(~0u, s1, 16);
            float i0v = 1.0f / s0, i1v = 1.0f / s1;
            float ca = e00 * i0v, cb = e01 * i0v;
            float cc = e10 * i1v, cd = e11 * i1v;
#pragma unroll
            for (int j = 0; j < 8; j++) {
                acc0[j] += ca * ua[j] + cc * va[j];
                acc1[j] += cb * ub[j] + cd * vb[j];
            }
        }

#pragma unroll
        for (int j = 0; j < 8; j++) {
            atomicAdd(&vs[o0 * 16 + fb + j], acc0[j]);
            atomicAdd(&vs[o1 * 16 + fb + j], acc1[j]);
        }
        __syncthreads();

        if (tid < 32) {
            float n2 = 0.f;
#pragma unroll
            for (int f = 0; f < 16; f++) { float t = vs[tid * 16 + f]; n2 += t * t; }
            scl[tid] = sqrtf(n2) / (1.0f + n2);
        }
        __syncthreads();

        if (it == 0) {
            float s0c = scl[o0], s1c = scl[o1];
#pragma unroll
            for (int j = 0; j < 8; j++) {
                vr0[j] = vs[o0 * 16 + fb + j] * s0c;
                vr1[j] = vs[o1 * 16 + fb + j] * s1c;
            }
            __syncthreads();   // all reads done before next-iter zeroing
        } else {
            out[b * NOF + tid] = vs[tid] * scl[tid >> 4];
        }
    }
}

extern "C" void kernel_launch(void* const* d_in, const int* in_sizes, int n_in,
                              void* d_out, int out_size) {
    const float* x = (const float*)d_in[0];   // [128, 512, 256]
    const float* W = (const float*)d_in[1];   // [1, 256, 512]
    float* out = (float*)d_out;               // [128, 32, 16]

    cudaFuncSetAttribute(gemm_tc, cudaFuncAttributeMaxDynamicSharedMemorySize, GEMM_SMEM);

    wt_kernel<<<256, 512>>>(W);                  // pre-swizzled tf32 B tiles
    gemm_tc<<<512, 512, GEMM_SMEM>>>(x, W);      // Uh (fp16) + fused iter-1 colsums
    squash_kernel<<<NB, 512>>>();                // v1 -> g_vsq (zeros g_vacc)
    route_fused<<<NB, 512>>>(out);               // iters 2+3 fused -> out
}

// round 11
// speedup vs baseline: 1.3886x; 1.1592x over previous
#include <cuda_runtime.h>
#include <cuda_fp16.h>
#include <cstdint>

#define NB 128
#define NI 512
#define NH 256
#define NOF 512   // O*F = 32*16

// Arch-feature gate: tcgen05 only exists in the sm_103a (arch-specific) pass.
#if defined(__CUDA_ARCH__) && \
    (defined(__CUDA_ARCH_FEAT_SM103_ALL) || defined(__CUDA_ARCH_FEAT_SM101_ALL) || \
     (defined(__CUDA_ARCH_SPECIFIC__) && (__CUDA_ARCH_SPECIFIC__ == 1030)))
#define TC_PATH 1
#else
#define TC_PATH 0
#endif

// ---------------- device scratch (allocation-free rule) ----------------
__device__ __half g_Uh[(size_t)NB * NI * NOF]; // u in fp16: [B*I, 512] row-major (64MB)
__device__ __half g_W2h[4 * 512 * 64];         // pre-swizzled fp16 B tiles: 4 chunks x 64KB
__device__ float g_vacc[NB * NOF];             // zero-init; squash re-zeros (replay-safe)
__device__ float g_vsq[NB * NOF];

// ---------------- generic helpers ----------------
__device__ __forceinline__ uint32_t smem_u32(const void* p) {
    uint32_t a;
    asm("{ .reg .u64 t; cvta.to.shared.u64 t, %1; cvt.u32.u64 %0, t; }" : "=r"(a) : "l"(p));
    return a;
}
__device__ __forceinline__ uint32_t sw128(uint32_t off) { return off ^ ((off >> 3) & 0x70); }
__device__ __forceinline__ uint32_t packh2(float a, float b) {
    __half2 h = __floats2half2_rn(a, b);
    return *reinterpret_cast<uint32_t*>(&h);
}

// packed f32x2 helpers (fallback GEMM)
__device__ __forceinline__ unsigned long long pack_dup(float a) {
    unsigned long long r;
    asm("mov.b64 %0, {%1, %1};" : "=l"(r) : "f"(a));
    return r;
}
__device__ __forceinline__ void ffma2(unsigned long long& d, unsigned long long a,
                                      unsigned long long b) {
    asm("fma.rn.f32x2 %0, %1, %2, %0;" : "+l"(d) : "l"(a), "l"(b));
}
__device__ __forceinline__ float2 unpack2(unsigned long long v) {
    float2 f;
    asm("mov.b64 {%0, %1}, %2;" : "=f"(f.x), "=f"(f.y) : "l"(v));
    return f;
}
// uint4 (8 fp16) -> 8 floats
__device__ __forceinline__ void cvt8(float* d, uint4 v) {
    __half2* h = (__half2*)&v;
#pragma unroll
    for (int k = 0; k < 4; k++) {
        float2 f = __half22float2(h[k]);
        d[2 * k] = f.x; d[2 * k + 1] = f.y;
    }
}
__device__ __forceinline__ float dot8(const float* a, const float* b) {
    float s = 0.f;
#pragma unroll
    for (int j = 0; j < 8; j++) s += a[j] * b[j];
    return s;
}

// -------- W -> pre-swizzled fp16 SMEM images: g_W2h[ch] = 64KB (512 n-rows x 128B) ------
// grid (4, 8), block 512: thread builds one 16B unit (8 K-halfs) for row n.
__global__ __launch_bounds__(512) void wt_kernel(const float* __restrict__ W) {
    int ch = blockIdx.x;
    int n = blockIdx.y * 64 + (threadIdx.x & 63);
    int jj = threadIdx.x >> 6;
    float f[8];
#pragma unroll
    for (int r = 0; r < 8; r++)
        f[r] = W[(size_t)(ch * 64 + jj * 8 + r) * NOF + n];
    uint4 h;
    h.x = packh2(f[0], f[1]); h.y = packh2(f[2], f[3]);
    h.z = packh2(f[4], f[5]); h.w = packh2(f[6], f[7]);
    *(uint4*)((char*)g_W2h + ch * 65536 + sw128((uint32_t)n * 128 + jj * 16)) = h;
}

// ---------------- SMEM layout for the GEMM kernel (1 CTA/SM) ----------------
#define SMB_TMEM 0
#define SMB_BF0 64
#define SMB_BF1 72
#define SMB_MD0 80
#define SMB_MD1 88
#define SM_CS 512                  // colsum: 64 floats
#define SM_A0 1024                 // A buf0: 16KB (128 rows x 128B fp16, K=64)
#define SM_A1 (SM_A0 + 16384)
#define SM_B0 (SM_A1 + 16384)      // 33792: B buf0 64KB
#define SM_B1 (SM_B0 + 65536)      // 99328: B buf1 64KB
#define GEMM_SMEM (SM_B1 + 65536 + 256)

#if TC_PATH
// ---------------- tcgen05-only PTX helpers ----------------
__device__ __forceinline__ uint32_t elect_one_pred() {
    uint32_t pred;
    asm volatile("{\n\t.reg .pred p;\n\telect.sync _|p, 0xFFFFFFFF;\n\t"
                 "selp.b32 %0, 1, 0, p;\n\t}" : "=r"(pred));
    return pred;
}
#define TCGEN05_ALLOC(sa, n) \
    asm volatile("tcgen05.alloc.cta_group::1.sync.aligned.shared::cta.b32 [%0], %1;" \
                 :: "r"((uint32_t)(sa)), "r"((uint32_t)(n)) : "memory")
#define TCGEN05_DEALLOC(t, n) \
    asm volatile("tcgen05.dealloc.cta_group::1.sync.aligned.b32 %0, %1;" :: "r"(t), "r"((uint32_t)(n)))
#define TCGEN05_RELINQ() \
    asm volatile("tcgen05.relinquish_alloc_permit.cta_group::1.sync.aligned;")
#define TCGEN05_COMMIT(mb) \
    asm volatile("tcgen05.commit.cta_group::1.mbarrier::arrive::one.shared::cluster.b64 [%0];" \
                 :: "r"((uint32_t)(mb)) : "memory")
#define TCGEN05_FENCE_AFTER() asm volatile("tcgen05.fence::after_thread_sync;" ::: "memory")
#define TCGEN05_FENCE_BEFORE() asm volatile("tcgen05.fence::before_thread_sync;" ::: "memory")
#define TCGEN05_WAIT_LD() asm volatile("tcgen05.wait::ld.sync.aligned;" ::: "memory")
#define FENCE_ASYNC_SHARED() asm volatile("fence.proxy.async.shared::cta;" ::: "memory")
#define MBAR_INIT(mb, c) \
    asm volatile("mbarrier.init.shared.b64 [%0], %1;" :: "r"((uint32_t)(mb)), "r"((uint32_t)(c)) : "memory")
#define MBAR_INVAL(mb) \
    asm volatile("mbarrier.inval.shared.b64 [%0];" :: "r"((uint32_t)(mb)) : "memory")
#define MBAR_EXPECT_TX(mb, bytes) \
    asm volatile("mbarrier.arrive.expect_tx.shared.b64 _, [%0], %1;" \
                 :: "r"((uint32_t)(mb)), "r"((uint32_t)(bytes)) : "memory")

__device__ __forceinline__ void mbar_wait_parity(uint32_t mb, uint32_t parity) {
    asm volatile(
        "{\n\t.reg .pred P1;\n\t"
        "WAIT_LOOP_%=:\n\t"
        "mbarrier.try_wait.parity.acquire.cta.shared::cta.b64 P1, [%0], %1, 0x989680;\n\t"
        "@P1 bra.uni WAIT_DONE_%=;\n\t"
        "bra.uni WAIT_LOOP_%=;\n\t"
        "WAIT_DONE_%=:\n\t}"
        :: "r"(mb), "r"(parity) : "memory");
}
__device__ __forceinline__ void bulk_ldg(uint32_t dst, const void* src, uint32_t bytes,
                                         uint32_t mb) {
    asm volatile(
        "cp.async.bulk.shared::cta.global.mbarrier::complete_tx::bytes [%0], [%1], %2, [%3];"
        :: "r"(dst), "l"(src), "r"(bytes), "r"(mb) : "memory");
}

#define LD32X32_X32(r, ta) \
    asm volatile( \
        "tcgen05.ld.sync.aligned.32x32b.x32.b32 " \
        "{%0, %1, %2, %3, %4, %5, %6, %7, %8, %9, %10, %11, %12, %13, %14, %15, " \
        " %16, %17, %18, %19, %20, %21, %22, %23, %24, %25, %26, %27, %28, %29, %30, %31}, [%32];" \
        : "=r"((r)[0]),  "=r"((r)[1]),  "=r"((r)[2]),  "=r"((r)[3]), \
          "=r"((r)[4]),  "=r"((r)[5]),  "=r"((r)[6]),  "=r"((r)[7]), \
          "=r"((r)[8]),  "=r"((r)[9]),  "=r"((r)[10]), "=r"((r)[11]), \
          "=r"((r)[12]), "=r"((r)[13]), "=r"((r)[14]), "=r"((r)[15]), \
          "=r"((r)[16]), "=r"((r)[17]), "=r"((r)[18]), "=r"((r)[19]), \
          "=r"((r)[20]), "=r"((r)[21]), "=r"((r)[22]), "=r"((r)[23]), \
          "=r"((r)[24]), "=r"((r)[25]), "=r"((r)[26]), "=r"((r)[27]), \
          "=r"((r)[28]), "=r"((r)[29]), "=r"((r)[30]), "=r"((r)[31]) \
        : "r"(ta))

__device__ __forceinline__ void mma_f16_ss(uint32_t d, uint64_t ad, uint64_t bd,
                                           uint32_t idesc, bool en) {
    uint32_t e = en ? 1u : 0u, z = 0u;
    asm volatile(
        "{\n\t.reg .pred p;\n\tsetp.ne.u32 p, %6, 0;\n\t"
        "tcgen05.mma.cta_group::1.kind::f16 [%0], %1, %2, %3, {%4, %4, %4, %4}, p;\n\t}"
        :: "r"(d), "l"(ad), "l"(bd), "r"(idesc), "r"(z), "r"(z), "r"(e)
        : "memory");
}
__device__ __forceinline__ uint64_t make_desc_sw128(uint32_t base) {
    const uint64_t BASE =
        (uint64_t(2) << 61) | (uint64_t(1) << 46) | (uint64_t(64) << 32) | (uint64_t(1) << 16);
    return BASE | ((uint64_t)(base >> 4) & 0x3FFF);
}
// idesc kind::f16: dtype F32=1<<4, atype=F16(0), btype=F16(0), N=256, M=128
#define F16_IDESC (0x10u | ((256u >> 3) << 17) | ((128u >> 4) << 24))
#endif  // TC_PATH

// -------- GEMM: Uh[65536,512] = X[65536,256] * W  (fp16 MMA, tile 128x512) --------------
// grid = 512, block = 512, 1 CTA/SM. 4 K-chunks of 64 (128B fp16 rows, SW128).
__global__ __launch_bounds__(512, 1) void gemm_tc(const float* __restrict__ X,
                                                  const float* __restrict__ W) {
    extern __shared__ char smem[];
    int tid = threadIdx.x;
    int rowBase = blockIdx.x << 7;
    int b = rowBase >> 9;

#if TC_PATH
    const uint32_t sb = smem_u32(smem);
    int wid = tid >> 5, lane = tid & 31;

    if (wid == 0) {
        TCGEN05_ALLOC(sb + SMB_TMEM, 512);
        TCGEN05_RELINQ();
    }
    if (tid == 0) {
        MBAR_INIT(sb + SMB_BF0, 1); MBAR_INIT(sb + SMB_BF1, 1);
        MBAR_INIT(sb + SMB_MD0, 1); MBAR_INIT(sb + SMB_MD1, 1);
    }
    __syncthreads();
    uint32_t tmem;
    asm volatile("ld.shared.b32 %0, [%1];" : "=r"(tmem) : "r"(sb + SMB_TMEM));

    // Prologue: A(0) regs (2 units x 8 floats), B(0) bulk (64KB)
    float4 ra[4];
#pragma unroll
    for (int p = 0; p < 2; p++) {
        int u = tid + (p << 9);
        const float* s = X + (size_t)(rowBase + (u >> 3)) * NH + (u & 7) * 8;
        ra[2 * p] = ((const float4*)s)[0];
        ra[2 * p + 1] = ((const float4*)s)[1];
    }
    if (tid == 0) {
        MBAR_EXPECT_TX(sb + SMB_BF0, 65536);
        bulk_ldg(sb + SM_B0, g_W2h, 65536, sb + SMB_BF0);
    }

    for (int ch = 0; ch < 4; ch++) {
        int buf = ch & 1;
        uint32_t Aoff = buf ? SM_A1 : SM_A0;
        uint32_t Boff = buf ? SM_B1 : SM_B0;
        uint32_t BFmb = sb + (buf ? SMB_BF1 : SMB_BF0);
        uint32_t MDmb = sb + (buf ? SMB_MD1 : SMB_MD0);

        // A regs -> SMEM fp16 (8 halfs = one 16B swizzle unit per store)
#pragma unroll
        for (int p = 0; p < 2; p++) {
            int u = tid + (p << 9);
            float4 v0 = ra[2 * p], v1 = ra[2 * p + 1];
            uint4 hv;
            hv.x = packh2(v0.x, v0.y); hv.y = packh2(v0.z, v0.w);
            hv.z = packh2(v1.x, v1.y); hv.w = packh2(v1.z, v1.w);
            *(uint4*)(smem + Aoff + sw128((u >> 3) * 128 + (u & 7) * 16)) = hv;
        }
        FENCE_ASYNC_SHARED();
        __syncthreads();

        if (wid == 0) {
            uint64_t ad = make_desc_sw128(sb + Aoff);
            uint64_t bd = make_desc_sw128(sb + Boff);
            if (elect_one_pred()) {
                mbar_wait_parity(BFmb, (ch >> 1) & 1);    // B(ch) arrived
#pragma unroll
                for (int h = 0; h < 2; h++)
#pragma unroll
                    for (int k = 0; k < 4; k++)   // K16 per dispatch, 4 per 64-K chunk
                        mma_f16_ss(tmem + h * 256, ad + k * 2, bd + h * 2048 + k * 2,
                                   F16_IDESC, (ch > 0) || (k > 0));
                TCGEN05_COMMIT(MDmb);
            }
        }

        // Prep chunk ch+1: wait MMA(ch-1) (frees nb buffers), overlap loads with MMA(ch)
        if (ch < 3) {
            int nb = (ch + 1) & 1;
            if (ch >= 1)
                mbar_wait_parity(sb + (nb ? SMB_MD1 : SMB_MD0), ((ch - 1) >> 1) & 1);
            int kk = (ch + 1) * 64;
#pragma unroll
            for (int p = 0; p < 2; p++) {
                int u = tid + (p << 9);
                const float* s = X + (size_t)(rowBase + (u >> 3)) * NH + kk + (u & 7) * 8;
                ra[2 * p] = ((const float4*)s)[0];
                ra[2 * p + 1] = ((const float4*)s)[1];
            }
            if (tid == 0) {
                uint32_t nBF = sb + (nb ? SMB_BF1 : SMB_BF0);
                MBAR_EXPECT_TX(nBF, 65536);
                bulk_ldg(sb + (nb ? SM_B1 : SM_B0),
                         (const char*)g_W2h + (ch + 1) * 65536, 65536, nBF);
            }
        }
    }
    mbar_wait_parity(sb + SMB_MD0, 1);   // MMA(2)
    mbar_wait_parity(sb + SMB_MD1, 1);   // MMA(3)
    TCGEN05_FENCE_AFTER();

    // Epilogue: 8 chunks of 64 cols. TMEM -> smt (pad 65) -> half2 GMEM + colsums.
    float* smt = (float*)(smem + SM_A0);      // 128 x 65 floats
    float* colsum = (float*)(smem + SM_CS);   // 64 floats
    for (int cc = 0; cc < 8; cc++) {
        if (tid < 64) colsum[tid] = 0.f;
        __syncthreads();
        if (wid < 4) {
            uint32_t regs[64];
            LD32X32_X32(regs, tmem + cc * 64);
            LD32X32_X32(regs + 32, tmem + cc * 64 + 32);
            TCGEN05_WAIT_LD();
            TCGEN05_FENCE_BEFORE();
            float* dst = smt + (wid * 32 + lane) * 65;
#pragma unroll
            for (int c = 0; c < 64; c++) dst[c] = __uint_as_float(regs[c]);
        }
        __syncthreads();
        int c2 = tid & 31, r0 = tid >> 5;     // col pair, 16 row groups
        float ls0 = 0.f, ls1 = 0.f;
        __half2* Uh2 = (__half2*)g_Uh;
#pragma unroll
        for (int p = 0; p < 8; p++) {
            int r = r0 + p * 16;
            float va = smt[r * 65 + 2 * c2];
            float vb = smt[r * 65 + 2 * c2 + 1];
            ls0 += va; ls1 += vb;
            Uh2[(size_t)(rowBase + r) * 256 + cc * 32 + c2] = __floats2half2_rn(va, vb);
        }
        atomicAdd(&colsum[2 * c2], ls0);
        atomicAdd(&colsum[2 * c2 + 1], ls1);
        __syncthreads();
        if (tid < 64)
            atomicAdd(&g_vacc[b * NOF + cc * 64 + tid], colsum[tid] * (1.0f / 32.0f));
    }

    __syncthreads();
    if (tid == 0) {
        MBAR_INVAL(sb + SMB_BF0); MBAR_INVAL(sb + SMB_BF1);
        MBAR_INVAL(sb + SMB_MD0); MBAR_INVAL(sb + SMB_MD1);
    }
    __syncthreads();
    if (wid == 0) TCGEN05_DEALLOC(tmem, 512);

#else  // ---------- FFMA2 fallback (plain sm_103 pass; same outputs, never selected) -----
    float* As = (float*)(smem);            // [8][128]
    float* Bs = (float*)(smem + 4096);     // [8][128]
    float* colsum = (float*)(smem + 8192); // [128]
    int tr = tid >> 5, tc = tid & 31;

    for (int ct = 0; ct < 4; ct++) {
        int colBase2 = ct * 128;
        unsigned long long acc[8][2];
#pragma unroll
        for (int i = 0; i < 8; i++) { acc[i][0] = 0ull; acc[i][1] = 0ull; }
        if (tid < 128) colsum[tid] = 0.f;
        __syncthreads();

        for (int kt = 0; kt < NH; kt += 8) {
#pragma unroll
            for (int q = 0; q < 2; q++) {
                int u = tid + q * 512;
                As[(u & 7) * 128 + (u >> 3)] =
                    X[(size_t)(rowBase + (u >> 3)) * NH + kt + (u & 7)];
                Bs[(u >> 7) * 128 + (u & 127)] =
                    W[(size_t)(kt + (u >> 7)) * NOF + colBase2 + (u & 127)];
            }
            __syncthreads();
#pragma unroll
            for (int k = 0; k < 8; k++) {
                const ulonglong2* bp = (const ulonglong2*)&Bs[k * 128 + tc * 4];
                ulonglong2 bb = bp[0];
                const float* ap = &As[k * 128 + tr * 8];
#pragma unroll
                for (int i = 0; i < 8; i++) {
                    unsigned long long m2 = pack_dup(ap[i]);
                    ffma2(acc[i][0], m2, bb.x);
                    ffma2(acc[i][1], m2, bb.y);
                }
            }
            __syncthreads();
        }
        float cs[4] = {0.f, 0.f, 0.f, 0.f};
#pragma unroll
        for (int i = 0; i < 8; i++) {
            float2 c0 = unpack2(acc[i][0]);
            float2 c1 = unpack2(acc[i][1]);
            __half2* Uh2 = (__half2*)g_Uh;
            size_t base = (size_t)(rowBase + tr * 8 + i) * 256 + (colBase2 + tc * 4) / 2;
            Uh2[base] = __floats2half2_rn(c0.x, c0.y);
            Uh2[base + 1] = __floats2half2_rn(c1.x, c1.y);
            cs[0] += c0.x; cs[1] += c0.y; cs[2] += c1.x; cs[3] += c1.y;
        }
#pragma unroll
        for (int j = 0; j < 4; j++) atomicAdd(&colsum[tc * 4 + j], cs[j]);
        __syncthreads();
        if (tid < 128)
            atomicAdd(&g_vacc[b * NOF + colBase2 + tid], colsum[tid] * (1.0f / 32.0f));
        __syncthreads();
    }
#endif
}

// ---------------- Squash v1: g_vsq = squash(g_vacc); re-zero g_vacc (replay-safe) --------
__global__ __launch_bounds__(512) void squash_kernel() {
    int idx = blockIdx.x * NOF + threadIdx.x;
    float val = g_vacc[idx];
    g_vacc[idx] = 0.f;
    float n2 = val * val;
#pragma unroll
    for (int m = 8; m > 0; m >>= 1)
        n2 += __shfl_xor_sync(~0u, n2, m);
    float scale = sqrtf(n2) / (1.0f + n2);
    g_vsq[idx] = val * scale;
}

// -------- Fused routing iters 2+3 on fp16 U: grid=NB (one CTA/batch), block=512 ----------
__global__ __launch_bounds__(512) void route_fused(float* __restrict__ out) {
    __shared__ float vs[NOF];
    __shared__ float scl[32];
    int b = blockIdx.x;
    int tid = threadIdx.x, warp = tid >> 5, lane = tid & 31;
    int o0 = lane >> 1, o1 = 16 + (lane >> 1);
    int fb = (lane & 1) << 3;

    float vr0[8], vr1[8];
    {
        const float* vp = g_vsq + b * NOF;
        float4 t0 = *(const float4*)(vp + lane * 8);
        float4 t1 = *(const float4*)(vp + lane * 8 + 4);
        float4 t2 = *(const float4*)(vp + 256 + lane * 8);
        float4 t3 = *(const float4*)(vp + 256 + lane * 8 + 4);
        vr0[0] = t0.x; vr0[1] = t0.y; vr0[2] = t0.z; vr0[3] = t0.w;
        vr0[4] = t1.x; vr0[5] = t1.y; vr0[6] = t1.z; vr0[7] = t1.w;
        vr1[0] = t2.x; vr1[1] = t2.y; vr1[2] = t2.z; vr1[3] = t2.w;
        vr1[4] = t3.x; vr1[5] = t3.y; vr1[6] = t3.z; vr1[7] = t3.w;
    }
    const __half* Ub = g_Uh + (size_t)b * NI * NOF;

    for (int it = 0; it < 2; it++) {
        vs[tid] = 0.f;
        __syncthreads();

        float acc0[8], acc1[8];
#pragma unroll
        for (int j = 0; j < 8; j++) { acc0[j] = 0.f; acc1[j] = 0.f; }

        for (int jj = 0; jj < 32; jj += 2) {
            int i0 = (warp << 5) + jj;
            const uint4* up = (const uint4*)(Ub + (size_t)i0 * NOF);
            uint4 xa = up[lane], xb = up[32 + lane];
            uint4 ya = up[64 + lane], yb = up[96 + lane];
            float ua[8], ub[8], va[8], vb[8];
            cvt8(ua, xa); cvt8(ub, xb); cvt8(va, ya); cvt8(vb, yb);

            float b0 = dot8(ua, vr0), b1 = dot8(ub, vr1);
            float d0 = dot8(va, vr0), d1 = dot8(vb, vr1);
            b0 += __shfl_xor_sync(~0u, b0, 1);
            b1 += __shfl_xor_sync(~0u, b1, 1);
            d0 += __shfl_xor_sync(~0u, d0, 1);
            d1 += __shfl_xor_sync(~0u, d1, 1);

            float e00 = __expf(b0), e01 = __expf(b1);
            float e10 = __expf(d0), e11 = __expf(d1);
            float s0 = e00 + e01, s1 = e10 + e11;
            s0 += __shfl_xor_sync(~0u, s0, 2);  s1 += __shfl_xor_sync(~0u, s1, 2);
            s0 += __shfl_xor_sync(~0u, s0, 4);  s1 += __shfl_xor_sync(~0u, s1, 4);
            s0 += __shfl_xor_sync(~0u, s0, 8);  s1 += __shfl_xor_sync(~0u, s1, 8);
            s0 += __shfl_xor_sync(~0u, s0, 16); s1 += __shfl_xor_sync(~0u, s1, 16);
            float i0v = 1.0f / s0, i1v = 1.0f / s1;
            float ca = e00 * i0v, cb = e01 * i0v;
            float cc = e10 * i1v, cd = e11 * i1v;
#pragma unroll
            for (int j = 0; j < 8; j++) {
                acc0[j] += ca * ua[j] + cc * va[j];
                acc1[j] += cb * ub[j] + cd * vb[j];
            }
        }

#pragma unroll
        for (int j = 0; j < 8; j++) {
            atomicAdd(&vs[o0 * 16 + fb + j], acc0[j]);
            atomicAdd(&vs[o1 * 16 + fb + j], acc1[j]);
        }
        __syncthreads();

        if (tid < 32) {
            float n2 = 0.f;
#pragma unroll
            for (int f = 0; f < 16; f++) { float t = vs[tid * 16 + f]; n2 += t * t; }
            scl[tid] = sqrtf(n2) / (1.0f + n2);
        }
        __syncthreads();

        if (it == 0) {
            float s0c = scl[o0], s1c = scl[o1];
#pragma unroll
            for (int j = 0; j < 8; j++) {
                vr0[j] = vs[o0 * 16 + fb + j] * s0c;
                vr1[j] = vs[o1 * 16 + fb + j] * s1c;
            }
            __syncthreads();
        } else {
            out[b * NOF + tid] = vs[tid] * scl[tid >> 4];
        }
    }
}

extern "C" void kernel_launch(void* const* d_in, const int* in_sizes, int n_in,
                              void* d_out, int out_size) {
    const float* x = (const float*)d_in[0];   // [128, 512, 256]
    const float* W = (const float*)d_in[1];   // [1, 256, 512]
    float* out = (float*)d_out;               // [128, 32, 16]

    cudaFuncSetAttribute(gemm_tc, cudaFuncAttributeMaxDynamicSharedMemorySize, GEMM_SMEM);

    wt_kernel<<<dim3(4, 8), 512>>>(W);           // pre-swizzled fp16 B tiles
    gemm_tc<<<512, 512, GEMM_SMEM>>>(x, W);      // Uh (fp16, f16 MMA) + iter-1 colsums
    squash_kernel<<<NB, 512>>>();                // v1 -> g_vsq (zeros g_vacc)
    route_fused<<<NB, 512>>>(out);               // iters 2+3 fused -> out
}